// round 3
// baseline (speedup 1.0000x reference)
#include <cuda_runtime.h>
#include <cuda_fp16.h>
#include <math.h>

// Problem constants
#define NB 128
#define LL 24
#define NN 121
#define DD 121
#define SSN 64
#define NSTEP 6
#define BL 3072
#define OUT_TOTAL (NSTEP*BL*NN)   // 2,230,272
#define STEP_SLAB (BL*NN)         // 371,712

// K1 config
#define K1_BLOCKS 32
#define K1_ROWS 96

// Transposed fp16 pack: for each matvec, warp-group w (outputs 4w..4w+3),
// row d: 4 halfs (uint2) at Wt[w*INp + d]. INp = padded input dim.
// Resident pack (halfs):
#define P_LIFT1 0          // 32*128*4 = 16384
#define P_LIFT2 16384      // 16384
#define P_NET1  32768      // 32*256*4 = 32768
#define P_NET2  65536      // 16384
#define P_FC1   81920      // 16384
#define HP_TOTAL 98304     // halfs -> 196,608 bytes

// dynamic smem byte offsets (after resident pack)
#define SM_BIAS  196608    // float[896] (7 x 128 padded biases)
#define SM_CAT   200192    // float[256]
#define SM_LIFT  201216    // float[128]
#define SM_NETH  201728    // float[128]
#define SM_XT    202240    // float[128]
#define SM_DELTA 202752    // float[128]
#define SM_BC    203264    // float[128]
#define SM_OUTV  203776    // float[128]
#define SM_FEAT  204288    // float[128]
#define SM_COMPW 204800    // float[320]
#define SM_RED   206080    // float[2048]
#define SMEM_BYTES 214272

// ---------------- device scratch ----------------
__device__ float d_gpart[K1_BLOCKS * 968];
__device__ float d_preds[NSTEP * DD];
__device__ __align__(16) __half d_hp[HP_TOTAL];     // smem-resident pack
__device__ __align__(16) __half d_p_fc23[16384];    // streamed
__device__ __align__(16) __half d_p_fout[16384];    // streamed

// ---------------- pack kernel: fp32 -> fp16 transposed ----------------
__global__ void kpack(const float* __restrict__ lw1, const float* __restrict__ lw2,
                      const float* __restrict__ nw1, const float* __restrict__ nw2,
                      const float* __restrict__ f1,  const float* __restrict__ fo,
                      const float* __restrict__ f2,  const float* __restrict__ f3) {
    int seg = blockIdx.x >> 5;      // 0..6
    int w = blockIdx.x & 31;
    int d = threadIdx.x;            // 0..255
    int c0 = 4 * w;
    float v[4];
    __half* dst = 0;
    int inp = 128;
    if (seg == 0) {                 // lift_w1 (121 x 128), INp=128
        if (d >= 128) return;
#pragma unroll
        for (int i = 0; i < 4; ++i) v[i] = (d < 121) ? lw1[d*128 + c0 + i] : 0.f;
        dst = d_hp + P_LIFT1;
    } else if (seg == 1) {          // lift_w2 (128 x 121), INp=128
        if (d >= 128) return;
#pragma unroll
        for (int i = 0; i < 4; ++i) v[i] = (c0 + i < 121) ? lw2[d*121 + c0 + i] : 0.f;
        dst = d_hp + P_LIFT2;
    } else if (seg == 2) {          // net_w1 (242 x 128), INp=256 reordered
        int r = (d < 121) ? d : ((d >= 128 && d < 249) ? d - 7 : -1);
#pragma unroll
        for (int i = 0; i < 4; ++i) v[i] = (r >= 0) ? nw1[r*128 + c0 + i] : 0.f;
        dst = d_hp + P_NET1;
        inp = 256;
    } else if (seg == 3) {          // net_w2 (128 x 121), INp=128
        if (d >= 128) return;
#pragma unroll
        for (int i = 0; i < 4; ++i) v[i] = (c0 + i < 121) ? nw2[d*121 + c0 + i] : 0.f;
        dst = d_hp + P_NET2;
    } else if (seg == 4) {          // fc1_w (121 x 121), INp=128
        if (d >= 128) return;
#pragma unroll
        for (int i = 0; i < 4; ++i)
            v[i] = (d < 121 && c0 + i < 121) ? f1[d*121 + c0 + i] : 0.f;
        dst = d_hp + P_FC1;
    } else if (seg == 5) {          // fc2|fc3 (121 x (64|64)), INp=128
        if (d >= 128) return;
#pragma unroll
        for (int i = 0; i < 4; ++i) {
            int c = c0 + i;
            v[i] = (d < 121) ? ((c < 64) ? f2[d*64 + c] : f3[d*64 + (c - 64)]) : 0.f;
        }
        dst = d_p_fc23;
    } else {                        // fcout_w (121 x 121), INp=128
        if (d >= 128) return;
#pragma unroll
        for (int i = 0; i < 4; ++i)
            v[i] = (d < 121 && c0 + i < 121) ? fo[d*121 + c0 + i] : 0.f;
        dst = d_p_fout;
    }
    __half2 h01 = __floats2half2_rn(v[0], v[1]);
    __half2 h23 = __floats2half2_rn(v[2], v[3]);
    uint2 u;
    u.x = *(unsigned int*)&h01;
    u.y = *(unsigned int*)&h23;
    ((uint2*)dst)[w*inp + d] = u;
}

// ---------------- K1: partial GEMM ----------------
__global__ void k1_gemm(const float* __restrict__ x, const float* __restrict__ cw) {
    __shared__ float cwsm[K1_ROWS * 8];
    int t = threadIdx.x;
    int r0 = blockIdx.x * K1_ROWS;
    for (int i = t; i < K1_ROWS * 8; i += 128) cwsm[i] = cw[r0*8 + i];
    __syncthreads();
    if (t < 121) {
        float acc[8];
#pragma unroll
        for (int j = 0; j < 8; ++j) acc[j] = 0.f;
#pragma unroll 4
        for (int r = 0; r < K1_ROWS; ++r) {
            float xv = x[(r0 + r)*121 + t];
#pragma unroll
            for (int j = 0; j < 8; ++j) acc[j] = fmaf(xv, cwsm[r*8 + j], acc[j]);
        }
#pragma unroll
        for (int j = 0; j < 8; ++j)
            d_gpart[blockIdx.x*968 + j*121 + t] = acc[j];
    }
}

// ---------------- activations ----------------
#define ACT_NONE 0
#define ACT_RELU 1
#define ACT_TANH 2
#define ACT_SOFTPLUS 3

template<int ACT>
__device__ __forceinline__ float actfn(float v) {
    if (ACT == ACT_RELU) return v > 0.f ? v : 0.f;
    if (ACT == ACT_TANH) return tanhf(v);
    if (ACT == ACT_SOFTPLUS) return v > 20.f ? v : log1pf(expf(v));
    return v;
}

// ---------------- warp-owns-outputs matvec ----------------
// Warp w computes outputs 4w..4w+3 over padded input (INW*32 rows).
// Wt layout: uint2 at [w*INW*32 + d]. One barrier at end.
template<int ACT, int INW>
__device__ __forceinline__ void wmv(const uint2* __restrict__ Wt,
                                    const float* __restrict__ biasp,
                                    const float* __restrict__ in,
                                    float* __restrict__ out) {
    int w = threadIdx.x >> 5, l = threadIdx.x & 31;
    const uint2* Wp = Wt + w*(INW*32) + l;
    float ax = 0.f, ay = 0.f, az = 0.f, aw = 0.f;
#pragma unroll
    for (int s = 0; s < INW; ++s) {
        float xv = in[s*32 + l];
        uint2 wv = Wp[s*32];
        float2 w01 = __half22float2(*(const __half2*)&wv.x);
        float2 w23 = __half22float2(*(const __half2*)&wv.y);
        ax = fmaf(xv, w01.x, ax);
        ay = fmaf(xv, w01.y, ay);
        az = fmaf(xv, w23.x, az);
        aw = fmaf(xv, w23.y, aw);
    }
#pragma unroll
    for (int off = 16; off; off >>= 1) {
        ax += __shfl_xor_sync(0xffffffffu, ax, off);
        ay += __shfl_xor_sync(0xffffffffu, ay, off);
        az += __shfl_xor_sync(0xffffffffu, az, off);
        aw += __shfl_xor_sync(0xffffffffu, aw, off);
    }
    if (l == 0) {
        float4 b = *(const float4*)(biasp + 4*w);
        float4 o;
        o.x = actfn<ACT>(ax + b.x);
        o.y = actfn<ACT>(ay + b.y);
        o.z = actfn<ACT>(az + b.z);
        o.w = actfn<ACT>(aw + b.w);
        *(float4*)(out + 4*w) = o;
    }
    __syncthreads();
}

// ---------------- K2: whole serial chain in one block ----------------
__global__ __launch_bounds__(1024, 1)
void k2_chain(const float* __restrict__ conv_b,
              const float* __restrict__ comp_w1, const float* __restrict__ comp_b1,
              const float* __restrict__ comp_w2, const float* __restrict__ comp_b2,
              const float* __restrict__ adapter_w, const float* __restrict__ adapter_b,
              const float* __restrict__ ln_g, const float* __restrict__ ln_b,
              const float* __restrict__ lift_b1, const float* __restrict__ lift_b2,
              const float* __restrict__ net_b1, const float* __restrict__ net_b2,
              const float* __restrict__ fc1_b,
              const float* __restrict__ fc2_b, const float* __restrict__ fc3_b,
              const float* __restrict__ Ag, const float* __restrict__ state_init,
              const float* __restrict__ fcout_b) {
    extern __shared__ __align__(16) unsigned char smraw[];
    float* biasp  = (float*)(smraw + SM_BIAS);
    float* cat    = (float*)(smraw + SM_CAT);
    float* lifted = (float*)(smraw + SM_LIFT);
    float* net_h  = (float*)(smraw + SM_NETH);
    float* xt_s   = (float*)(smraw + SM_XT);
    float* delta_s= (float*)(smraw + SM_DELTA);
    float* bc     = (float*)(smraw + SM_BC);
    float* outv   = (float*)(smraw + SM_OUTV);
    float* feat   = (float*)(smraw + SM_FEAT);
    float* compw  = (float*)(smraw + SM_COMPW);
    float* red    = (float*)(smraw + SM_RED);

    const uint2* W_lift1 = (const uint2*)(smraw + P_LIFT1*2);
    const uint2* W_lift2 = (const uint2*)(smraw + P_LIFT2*2);
    const uint2* W_net1  = (const uint2*)(smraw + P_NET1*2);
    const uint2* W_net2  = (const uint2*)(smraw + P_NET2*2);
    const uint2* W_fc1   = (const uint2*)(smraw + P_FC1*2);
    const uint2* W_fc23  = (const uint2*)d_p_fc23;
    const uint2* W_fout  = (const uint2*)d_p_fout;

    int tid = threadIdx.x;

    // --- 0. load resident weight pack (196,608 B = 12,288 uint4) ---
    {
        const uint4* src = (const uint4*)d_hp;
        uint4* dst = (uint4*)smraw;
#pragma unroll 4
        for (int i = tid; i < HP_TOTAL/8; i += 1024) dst[i] = src[i];
    }

    // --- 1. reduce GEMM partials -> g in red[n*8+j] ---
    if (tid < 968) {
        int j = tid / 121, n = tid % 121;
        float v = conv_b[j];
#pragma unroll 4
        for (int b = 0; b < K1_BLOCKS; ++b) v += d_gpart[b*968 + tid];
        red[n*8 + j] = v;
    }
    __syncthreads();
    // compressor weights (fold [g,g] dup) + padded biases
    if (tid < 256) compw[tid] = comp_w1[tid] + comp_w1[256 + tid];
    else if (tid < 288) compw[tid] = comp_b1[tid - 256];
    else if (tid < 320) compw[tid] = comp_w2[tid - 288];
    if (tid < 896) {
        int seg = tid >> 7, j = tid & 127;
        float v = 0.f;
        if (seg == 0) v = lift_b1[j];
        else if (seg == 1) v = (j < 121) ? lift_b2[j] : 0.f;
        else if (seg == 2) v = net_b1[j];
        else if (seg == 3) v = (j < 121) ? net_b2[j] : 0.f;
        else if (seg == 4) v = (j < 121) ? fc1_b[j] : 0.f;
        else if (seg == 5) v = (j < 64) ? fc2_b[j] : fc3_b[j - 64];
        else v = (j < 121) ? fcout_b[j] : 0.f;
        biasp[tid] = v;
    }
    // zero pads once: cat[121..127], outv[121..127]
    if (tid >= 121 && tid < 128) { cat[tid] = 0.f; outv[tid] = 0.f; }
    __syncthreads();

    // --- 2. feature compressor -> feat[n] ---
    if (tid < 121) {
        float gv[8];
#pragma unroll
        for (int j = 0; j < 8; ++j) gv[j] = red[tid*8 + j];
        float f = comp_b2[0];
#pragma unroll 4
        for (int k = 0; k < 32; ++k) {
            float hh = compw[256 + k];
#pragma unroll
            for (int i = 0; i < 8; ++i) hh = fmaf(gv[i], compw[i*32 + k], hh);
            hh = hh > 0.f ? hh : 0.01f * hh;
            f = fmaf(hh, compw[288 + k], f);
        }
        feat[tid] = f;
    }
    __syncthreads();

    // --- 3. adapter matvec (one-time) ---
    if (tid < 121) {
        float v = adapter_b[tid];
        for (int n = 0; n < 121; ++n) v = fmaf(feat[n], adapter_w[n*121 + tid], v);
        outv[tid] = v;
    }
    __syncthreads();

    // --- 4. layernorm -> q = cat[0..120] ---
    {
        float zv = (tid < 121) ? outv[tid] : 0.f;
        red[tid] = zv;
        red[1024 + tid] = zv * zv;
        __syncthreads();
        for (int off = 512; off > 0; off >>= 1) {
            if (tid < off) {
                red[tid] += red[tid + off];
                red[1024 + tid] += red[1024 + tid + off];
            }
            __syncthreads();
        }
        float mu = red[0] * (1.f / 121.f);
        float var = red[1024] * (1.f / 121.f) - mu * mu;
        float rstd = rsqrtf(var + 1e-5f);
        if (tid < 121) cat[tid] = (outv[tid] - mu) * rstd * ln_g[tid] + ln_b[tid];
        if (tid < 121) outv[tid] = 0.f;  // restore (only pads matter; real vals rewritten)
    }

    // --- 5. state h + A in registers: tid<968 holds h[d=tid>>3][(tid&7)*8..+7] ---
    float h[8], av[8];
    int sd = tid >> 3, s8 = tid & 7;
    int hbase = sd * 64 + s8 * 8;
    if (tid < 968) {
        float4 h0 = *(const float4*)(state_init + hbase);
        float4 h1 = *(const float4*)(state_init + hbase + 4);
        h[0]=h0.x; h[1]=h0.y; h[2]=h0.z; h[3]=h0.w;
        h[4]=h1.x; h[5]=h1.y; h[6]=h1.z; h[7]=h1.w;
        float4 a0 = *(const float4*)(Ag + hbase);
        float4 a1 = *(const float4*)(Ag + hbase + 4);
        av[0]=a0.x; av[1]=a0.y; av[2]=a0.z; av[3]=a0.w;
        av[4]=a1.x; av[5]=a1.y; av[6]=a1.z; av[7]=a1.w;
    }
    __syncthreads();

    // --- 6. 7 serial mamba iterations (iter 0 = warmup) ---
    for (int it = 0; it < 7; ++it) {
        wmv<ACT_RELU, 4>(W_lift1, biasp + 0,   cat,    lifted);
        wmv<ACT_TANH, 4>(W_lift2, biasp + 128, lifted, cat + 128);
        wmv<ACT_RELU, 8>(W_net1,  biasp + 256, cat,    net_h);
        wmv<ACT_NONE, 4>(W_net2,  biasp + 384, net_h,  xt_s);
        wmv<ACT_SOFTPLUS, 4>(W_fc1, biasp + 512, xt_s, delta_s);
        wmv<ACT_NONE, 4>(W_fc23,  biasp + 640, xt_s,   bc);

        // state update + partial out
        if (tid < 968) {
            float dl = delta_s[sd];
            float xd = xt_s[sd] * dl;
            float po = 0.f;
#pragma unroll
            for (int j = 0; j < 8; ++j) {
                float z = dl * av[j];
                float cel = z > 0.f ? z : expm1f(z);
                float dA = expf(-cel);
                float hn = fmaf(dA, h[j], xd * bc[s8*8 + j]);
                h[j] = hn;
                po = fmaf(bc[64 + s8*8 + j], hn, po);
            }
            red[tid] = po;
        }
        __syncthreads();
        if (tid < 121) {
            float v = 0.f;
#pragma unroll
            for (int s2 = 0; s2 < 8; ++s2) v += red[tid*8 + s2];
            outv[tid] = v;
        }
        __syncthreads();

        if (it > 0) {
            wmv<ACT_NONE, 4>(W_fout, biasp + 768, outv, cat);
            if (tid < 121) d_preds[(it - 1)*121 + tid] = cat[tid];
        }
        // it == 0: q (cat[0..127]) untouched -> stays z0
    }
}

// ---------------- K3: coalesced broadcast ----------------
// 3872 float4 per block (== 32*121, so block base ≡ 0 mod 121). 24 blocks/step.
__global__ __launch_bounds__(512)
void k3_bcast(float4* __restrict__ out) {
    __shared__ __align__(16) float tile[484];
    int b = blockIdx.x;
    int step = b / 24;
    int t = threadIdx.x;
    if (t < 484) tile[t] = d_preds[step*121 + (t % 121)];
    __syncthreads();
    const float4* t4 = (const float4*)tile;
    long base = (long)b * 3872;
    int m = t % 121;
#pragma unroll
    for (int i = 0; i < 7; ++i) {
        out[base + t + 512*i] = t4[m];
        m += 28; if (m >= 121) m -= 121;
    }
    if (t < 288) out[base + t + 3584] = t4[m];
}

// ---------------- launch ----------------
extern "C" void kernel_launch(void* const* d_in, const int* in_sizes, int n_in,
                              void* d_out, int out_size) {
    const float* x          = (const float*)d_in[0];
    const float* conv_w     = (const float*)d_in[3];
    const float* conv_b     = (const float*)d_in[4];
    const float* comp_w1    = (const float*)d_in[5];
    const float* comp_b1    = (const float*)d_in[6];
    const float* comp_w2    = (const float*)d_in[7];
    const float* comp_b2    = (const float*)d_in[8];
    const float* adapter_w  = (const float*)d_in[9];
    const float* adapter_b  = (const float*)d_in[10];
    const float* ln_g       = (const float*)d_in[11];
    const float* ln_b       = (const float*)d_in[12];
    const float* lift_w1    = (const float*)d_in[13];
    const float* lift_b1    = (const float*)d_in[14];
    const float* lift_w2    = (const float*)d_in[15];
    const float* lift_b2    = (const float*)d_in[16];
    const float* net_w1     = (const float*)d_in[17];
    const float* net_b1     = (const float*)d_in[18];
    const float* net_w2     = (const float*)d_in[19];
    const float* net_b2     = (const float*)d_in[20];
    const float* fc1_w      = (const float*)d_in[21];
    const float* fc1_b      = (const float*)d_in[22];
    const float* fc2_w      = (const float*)d_in[23];
    const float* fc2_b      = (const float*)d_in[24];
    const float* fc3_w      = (const float*)d_in[25];
    const float* fc3_b      = (const float*)d_in[26];
    const float* A          = (const float*)d_in[27];
    const float* state_init = (const float*)d_in[28];
    const float* fcout_w    = (const float*)d_in[29];
    const float* fcout_b    = (const float*)d_in[30];
    (void)in_sizes; (void)n_in;

    static int smem_set = 0;
    if (!smem_set) {
        cudaFuncSetAttribute(k2_chain, cudaFuncAttributeMaxDynamicSharedMemorySize, SMEM_BYTES);
        smem_set = 1;
    }

    kpack<<<224, 256>>>(lift_w1, lift_w2, net_w1, net_w2, fc1_w, fcout_w, fc2_w, fc3_w);
    k1_gemm<<<K1_BLOCKS, 128>>>(x, conv_w);
    k2_chain<<<1, 1024, SMEM_BYTES>>>(conv_b, comp_w1, comp_b1, comp_w2, comp_b2,
                                      adapter_w, adapter_b, ln_g, ln_b,
                                      lift_b1, lift_b2, net_b1, net_b2,
                                      fc1_b, fc2_b, fc3_b,
                                      A, state_init, fcout_b);
    k3_bcast<<<144, 512>>>((float4*)d_out);
}

// round 4
// speedup vs baseline: 1.1920x; 1.1920x over previous
#include <cuda_runtime.h>
#include <cuda_fp16.h>
#include <math.h>

// Problem constants
#define NB 128
#define LL 24
#define NN 121
#define DD 121
#define NSTEP 6
#define BL 3072
#define OUT_TOTAL (NSTEP*BL*NN)
#define STEP_SLAB (BL*NN)

// K1 config
#define K1_BLOCKS 32
#define K1_ROWS 96

// Resident pack bases in uint units (each 128-IN matvec: 8192 uints = 16384 halfs)
#define UB_L1 0
#define UB_L2 8192
#define UB_N1 16384      // net1: 2 chunks -> 16384 uints
#define UB_N2 32768
#define UB_F1 40960
#define UPK_TOTAL 49152  // uints -> 196608 bytes

// smem byte offsets
#define SB_PACK   0
#define SB_BIAS   196608   // float[896]
#define SB_RED    200192   // float[4096]
#define SB_CATH2  216576   // uint[256]
#define SB_L1H2   217600   // uint[128]
#define SB_NETH2  218112   // uint[128]
#define SB_XTH2   218624   // uint[128]
#define SB_XTF    219136   // float[128]
#define SB_DELTA  219648   // float[128]
#define SB_BC     220160   // float[128]
#define SB_OUTV   220672   // float[128]
#define SB_OUTVH2 221184   // uint[128]
#define SB_FEAT   221696   // float[128]
#define SB_COMPW  222208   // float[320]
#define SB_DUMMYF 223488   // float[128]
#define SMEM_BYTES 224000

// ---------------- device scratch ----------------
__device__ float d_gpart[K1_BLOCKS * 968];
__device__ float d_preds[NSTEP * DD];
__device__ __align__(16) unsigned int d_hpack[UPK_TOTAL];
__device__ __align__(16) unsigned int d_pk_fc23[8192];
__device__ __align__(16) unsigned int d_pk_fout[8192];

// ---------------- K0: fused k1 partial GEMM + weight packing ----------------
__global__ __launch_bounds__(256)
void k0(const float* __restrict__ x, const float* __restrict__ cw,
        const float* __restrict__ lw1, const float* __restrict__ lw2,
        const float* __restrict__ nw1, const float* __restrict__ nw2,
        const float* __restrict__ f1,  const float* __restrict__ f2,
        const float* __restrict__ f3,  const float* __restrict__ fo) {
    int b = blockIdx.x;
    int t = threadIdx.x;
    if (b < K1_BLOCKS) {
        // ---- k1: g partials ----
        __shared__ float cwsm[K1_ROWS * 8];
        int r0 = b * K1_ROWS;
        for (int j = t; j < K1_ROWS * 8; j += 256) cwsm[j] = cw[r0*8 + j];
        __syncthreads();
        if (t < 121) {
            float acc[8];
#pragma unroll
            for (int j = 0; j < 8; ++j) acc[j] = 0.f;
#pragma unroll 4
            for (int r = 0; r < K1_ROWS; ++r) {
                float xv = x[(r0 + r)*121 + t];
#pragma unroll
                for (int j = 0; j < 8; ++j) acc[j] = fmaf(xv, cwsm[r*8 + j], acc[j]);
            }
#pragma unroll
            for (int j = 0; j < 8; ++j)
                d_gpart[b*968 + j*121 + t] = acc[j];
        }
        return;
    }
    // ---- pack: per (matrix, slice sg): 32 q-groups x 16 halfs ----
    int p = b - K1_BLOCKS;
    int q = t & 31, i = t >> 5;        // i: 0..7 (uint index within (s,q))
    int dl = i >> 1;                   // d_local 0..3
    int ol = (2*i) & 3;                // 0 or 2
    int m, sg;
    if      (p < 32)  { m = 0; sg = p; }
    else if (p < 64)  { m = 1; sg = p - 32; }
    else if (p < 128) { m = 2; sg = p - 64; }
    else if (p < 160) { m = 3; sg = p - 128; }
    else if (p < 192) { m = 4; sg = p - 160; }
    else if (p < 224) { m = 5; sg = p - 192; }
    else              { m = 6; sg = p - 224; }
    int k = sg*4 + dl;                 // packed input index
    int row, rvalid;
    if (m == 2) {
        row = (k < 128) ? k : (121 + (k - 128));
        rvalid = (k < 128) ? (k < 121) : ((k - 128) < 121);
    } else {
        row = k;
        rvalid = (k < ((m == 1 || m == 3) ? 128 : 121));
    }
    int o0 = q*4 + ol, o1 = o0 + 1;
    float v0 = 0.f, v1 = 0.f;
    if (rvalid) {
        switch (m) {
            case 0: v0 = lw1[row*128 + o0]; v1 = lw1[row*128 + o1]; break;
            case 1: v0 = (o0 < 121) ? lw2[row*121 + o0] : 0.f;
                    v1 = (o1 < 121) ? lw2[row*121 + o1] : 0.f; break;
            case 2: v0 = nw1[row*128 + o0]; v1 = nw1[row*128 + o1]; break;
            case 3: v0 = (o0 < 121) ? nw2[row*121 + o0] : 0.f;
                    v1 = (o1 < 121) ? nw2[row*121 + o1] : 0.f; break;
            case 4: v0 = (o0 < 121) ? f1[row*121 + o0] : 0.f;
                    v1 = (o1 < 121) ? f1[row*121 + o1] : 0.f; break;
            case 5: v0 = (o0 < 64) ? f2[row*64 + o0] : f3[row*64 + o0 - 64];
                    v1 = (o1 < 64) ? f2[row*64 + o1] : f3[row*64 + o1 - 64]; break;
            default:v0 = (o0 < 121) ? fo[row*121 + o0] : 0.f;
                    v1 = (o1 < 121) ? fo[row*121 + o1] : 0.f; break;
        }
    }
    __half2 hh = __floats2half2_rn(v0, v1);
    unsigned u = *(unsigned*)&hh;
    unsigned* dp; unsigned base;
    switch (m) {
        case 0: dp = d_hpack;   base = UB_L1; break;
        case 1: dp = d_hpack;   base = UB_L2; break;
        case 2: dp = d_hpack;   base = UB_N1; break;
        case 3: dp = d_hpack;   base = UB_N2; break;
        case 4: dp = d_hpack;   base = UB_F1; break;
        case 5: dp = d_pk_fc23; base = 0; break;
        default:dp = d_pk_fout; base = 0; break;
    }
    dp[base + (unsigned)(sg*32 + q)*8u + i] = u;
}

// ---------------- activations ----------------
#define ACT_NONE 0
#define ACT_RELU 1
#define ACT_TANH 2
#define ACT_SOFTPLUS 3

template<int ACT>
__device__ __forceinline__ float actfn(float v) {
    if (ACT == ACT_RELU) return v > 0.f ? v : 0.f;
    if (ACT == ACT_TANH) return tanhf(v);
    if (ACT == ACT_SOFTPLUS) return v > 20.f ? v : log1pf(expf(v));
    return v;
}

// ---------------- cp.async helpers ----------------
__device__ __forceinline__ void cp_async16(void* smem_dst, const void* gsrc) {
    unsigned saddr = (unsigned)__cvta_generic_to_shared(smem_dst);
    asm volatile("cp.async.cg.shared.global [%0], [%1], 16;" :: "r"(saddr), "l"(gsrc));
}

// ---------------- half2 matvec: 128 outputs, 32 slices x 4 inputs ----------------
// Wt: uint4 pack, per (chunk,s,q): 2 uint4 = 16 halfs = 4 rows x 4 outs.
// inh2: dup-half2 per input element.
template<int ACT, int CHUNKS>
__device__ __forceinline__ void mvh(const uint4* __restrict__ Wt,
                                    const float* __restrict__ biasp,
                                    const unsigned* __restrict__ inh2,
                                    float* __restrict__ outf,
                                    unsigned* __restrict__ outh2,
                                    float* __restrict__ red) {
    int tid = threadIdx.x;
    int q = tid & 31, s = tid >> 5;
    float2 a01 = make_float2(0.f, 0.f), a23 = make_float2(0.f, 0.f);
#pragma unroll
    for (int c = 0; c < CHUNKS; ++c) {
        uint4 xh = ((const uint4*)inh2)[c*32 + s];
        const uint4* wp = Wt + ((c*32 + s)*32 + q)*2;
        uint4 w0 = wp[0];
        uint4 w1 = wp[1];
        __half2 x0 = *(__half2*)&xh.x, x1 = *(__half2*)&xh.y;
        __half2 x2 = *(__half2*)&xh.z, x3 = *(__half2*)&xh.w;
        __half2 p01 = __hfma2(x0, *(__half2*)&w0.x, __hmul2(x1, *(__half2*)&w0.z));
        __half2 p23 = __hfma2(x0, *(__half2*)&w0.y, __hmul2(x1, *(__half2*)&w0.w));
        float2 f;
        f = __half22float2(p01); a01.x += f.x; a01.y += f.y;
        f = __half22float2(p23); a23.x += f.x; a23.y += f.y;
        p01 = __hfma2(x2, *(__half2*)&w1.x, __hmul2(x3, *(__half2*)&w1.z));
        p23 = __hfma2(x2, *(__half2*)&w1.y, __hmul2(x3, *(__half2*)&w1.w));
        f = __half22float2(p01); a01.x += f.x; a01.y += f.y;
        f = __half22float2(p23); a23.x += f.x; a23.y += f.y;
    }
    ((float4*)red)[s*32 + q] = make_float4(a01.x, a01.y, a23.x, a23.y);
    __syncthreads();
    if (tid < 128) {
        float v = 0.f;
#pragma unroll
        for (int ss = 0; ss < 32; ++ss) v += red[ss*128 + tid];
        v += biasp[tid];
        v = actfn<ACT>(v);
        outf[tid] = v;
        __half2 d2 = __half2half2(__float2half_rn(v));
        outh2[tid] = *(unsigned*)&d2;
    }
    __syncthreads();
}

// ---------------- K2: whole serial chain in one block ----------------
__global__ __launch_bounds__(1024, 1)
void k2_chain(const float* __restrict__ conv_b,
              const float* __restrict__ comp_w1, const float* __restrict__ comp_b1,
              const float* __restrict__ comp_w2, const float* __restrict__ comp_b2,
              const float* __restrict__ adapter_w, const float* __restrict__ adapter_b,
              const float* __restrict__ ln_g, const float* __restrict__ ln_b,
              const float* __restrict__ lift_b1, const float* __restrict__ lift_b2,
              const float* __restrict__ net_b1, const float* __restrict__ net_b2,
              const float* __restrict__ fc1_b,
              const float* __restrict__ fc2_b, const float* __restrict__ fc3_b,
              const float* __restrict__ Ag, const float* __restrict__ state_init,
              const float* __restrict__ fcout_b) {
    extern __shared__ __align__(16) unsigned char smraw[];
    float*    biasp   = (float*)(smraw + SB_BIAS);
    float*    red     = (float*)(smraw + SB_RED);
    unsigned* cath2   = (unsigned*)(smraw + SB_CATH2);
    unsigned* l1h2    = (unsigned*)(smraw + SB_L1H2);
    unsigned* neth2   = (unsigned*)(smraw + SB_NETH2);
    unsigned* xth2    = (unsigned*)(smraw + SB_XTH2);
    float*    xtf     = (float*)(smraw + SB_XTF);
    float*    delta_s = (float*)(smraw + SB_DELTA);
    float*    bc      = (float*)(smraw + SB_BC);
    float*    outv    = (float*)(smraw + SB_OUTV);
    unsigned* outvh2  = (unsigned*)(smraw + SB_OUTVH2);
    float*    feat    = (float*)(smraw + SB_FEAT);
    float*    compw   = (float*)(smraw + SB_COMPW);
    float*    dummyf  = (float*)(smraw + SB_DUMMYF);

    const uint4* W_L1 = (const uint4*)(smraw + UB_L1*4);
    const uint4* W_L2 = (const uint4*)(smraw + UB_L2*4);
    const uint4* W_N1 = (const uint4*)(smraw + UB_N1*4);
    const uint4* W_N2 = (const uint4*)(smraw + UB_N2*4);
    const uint4* W_F1 = (const uint4*)(smraw + UB_F1*4);
    const uint4* W_FC23 = (const uint4*)d_pk_fc23;
    const uint4* W_FOUT = (const uint4*)d_pk_fout;

    int tid = threadIdx.x;

    // --- 0. async prefetch of resident pack into smem (overlaps prologue) ---
    {
        const uint4* src = (const uint4*)d_hpack;
        for (int i = tid; i < UPK_TOTAL/4; i += 1024)
            cp_async16((uint4*)smraw + i, src + i);
        asm volatile("cp.async.commit_group;");
    }

    // --- 1. reduce GEMM partials -> g in red[n*8+j] ---
    if (tid < 968) {
        int j = tid / 121, n = tid % 121;
        float v = conv_b[j];
#pragma unroll 4
        for (int b = 0; b < K1_BLOCKS; ++b) v += d_gpart[b*968 + tid];
        red[n*8 + j] = v;
    }
    __syncthreads();
    if (tid < 256) compw[tid] = comp_w1[tid] + comp_w1[256 + tid];
    else if (tid < 288) compw[tid] = comp_b1[tid - 256];
    else if (tid < 320) compw[tid] = comp_w2[tid - 288];
    if (tid < 896) {
        int seg = tid >> 7, j = tid & 127;
        float v = 0.f;
        if (seg == 0) v = lift_b1[j];
        else if (seg == 1) v = (j < 121) ? lift_b2[j] : 0.f;
        else if (seg == 2) v = net_b1[j];
        else if (seg == 3) v = (j < 121) ? net_b2[j] : 0.f;
        else if (seg == 4) v = (j < 121) ? fc1_b[j] : 0.f;
        else if (seg == 5) v = (j < 64) ? fc2_b[j] : fc3_b[j - 64];
        else v = (j < 121) ? fcout_b[j] : 0.f;
        biasp[tid] = v;
    }
    if (tid >= 121 && tid < 128) { cath2[tid] = 0u; outvh2[tid] = 0u; }
    __syncthreads();

    // --- 2. feature compressor -> feat[n] ---
    if (tid < 121) {
        float gv[8];
#pragma unroll
        for (int j = 0; j < 8; ++j) gv[j] = red[tid*8 + j];
        float f = comp_b2[0];
#pragma unroll 4
        for (int kk = 0; kk < 32; ++kk) {
            float hh = compw[256 + kk];
#pragma unroll
            for (int i = 0; i < 8; ++i) hh = fmaf(gv[i], compw[i*32 + kk], hh);
            hh = hh > 0.f ? hh : 0.01f * hh;
            f = fmaf(hh, compw[288 + kk], f);
        }
        feat[tid] = f;
    }
    __syncthreads();

    // --- 3. adapter matvec (one-time) ---
    if (tid < 121) {
        float v = adapter_b[tid];
        for (int n = 0; n < 121; ++n) v = fmaf(feat[n], adapter_w[n*121 + tid], v);
        outv[tid] = v;
    }
    __syncthreads();

    // --- 4. layernorm -> q into cath2[0..120] (dup-half2) ---
    {
        float zv = (tid < 121) ? outv[tid] : 0.f;
        red[tid] = zv;
        red[1024 + tid] = zv * zv;
        __syncthreads();
        for (int off = 512; off > 0; off >>= 1) {
            if (tid < off) {
                red[tid] += red[tid + off];
                red[1024 + tid] += red[1024 + tid + off];
            }
            __syncthreads();
        }
        float mu = red[0] * (1.f / 121.f);
        float var = red[1024] * (1.f / 121.f) - mu * mu;
        float rstd = rsqrtf(var + 1e-5f);
        if (tid < 121) {
            float qv = (outv[tid] - mu) * rstd * ln_g[tid] + ln_b[tid];
            __half2 d2 = __half2half2(__float2half_rn(qv));
            cath2[tid] = *(unsigned*)&d2;
        }
    }

    // --- 5. state h + A in registers ---
    float h[8], av[8];
    int sd = tid >> 3, s8 = tid & 7;
    int hbase = sd * 64 + s8 * 8;
    if (tid < 968) {
        float4 h0 = *(const float4*)(state_init + hbase);
        float4 h1 = *(const float4*)(state_init + hbase + 4);
        h[0]=h0.x; h[1]=h0.y; h[2]=h0.z; h[3]=h0.w;
        h[4]=h1.x; h[5]=h1.y; h[6]=h1.z; h[7]=h1.w;
        float4 a0 = *(const float4*)(Ag + hbase);
        float4 a1 = *(const float4*)(Ag + hbase + 4);
        av[0]=a0.x; av[1]=a0.y; av[2]=a0.z; av[3]=a0.w;
        av[4]=a1.x; av[5]=a1.y; av[6]=a1.z; av[7]=a1.w;
    }
    asm volatile("cp.async.wait_group 0;");
    __syncthreads();

    // --- 6. 7 serial mamba iterations (iter 0 = warmup) ---
#pragma unroll 1
    for (int it = 0; it < 7; ++it) {
        mvh<ACT_RELU, 1>(W_L1, biasp + 0,   cath2, dummyf, l1h2,        red);
        mvh<ACT_TANH, 1>(W_L2, biasp + 128, l1h2,  dummyf, cath2 + 128, red);
        mvh<ACT_RELU, 2>(W_N1, biasp + 256, cath2, dummyf, neth2,       red);
        mvh<ACT_NONE, 1>(W_N2, biasp + 384, neth2, xtf,    xth2,        red);
        mvh<ACT_SOFTPLUS, 1>(W_F1, biasp + 512, xth2, delta_s, l1h2,    red);
        mvh<ACT_NONE, 1>(W_FC23, biasp + 640, xth2, bc, l1h2,           red);

        // state update + partial out
        if (tid < 968) {
            float dl = delta_s[sd];
            float xd = xtf[sd] * dl;
            float po = 0.f;
#pragma unroll
            for (int j = 0; j < 8; ++j) {
                float z = dl * av[j];
                float cel = z > 0.f ? z : expm1f(z);
                float dA = expf(-cel);
                float hn = fmaf(dA, h[j], xd * bc[s8*8 + j]);
                h[j] = hn;
                po = fmaf(bc[64 + s8*8 + j], hn, po);
            }
            red[tid] = po;
        }
        __syncthreads();
        if (tid < 121) {
            float v = 0.f;
#pragma unroll
            for (int s2 = 0; s2 < 8; ++s2) v += red[tid*8 + s2];
            outv[tid] = v;
            __half2 d2 = __half2half2(__float2half_rn(v));
            outvh2[tid] = *(unsigned*)&d2;
        }
        __syncthreads();

        if (it > 0) {
            mvh<ACT_NONE, 1>(W_FOUT, biasp + 768, outvh2, dummyf, cath2, red);
            if (tid < 121) d_preds[(it - 1)*121 + tid] = dummyf[tid];
        }
        // it == 0: q (cath2[0..127]) untouched -> stays z0
    }
}

// ---------------- K3: coalesced broadcast (576 blocks x 256 thr) ----------------
// Each block writes 968 float4 (= 8*121), 96 blocks per step.
__global__ __launch_bounds__(256)
void k3_bcast(float4* __restrict__ out) {
    __shared__ __align__(16) float tile[484];
    int b = blockIdx.x;
    int step = b / 96;
    int r = b - step * 96;
    int t = threadIdx.x;
    for (int i = t; i < 484; i += 256) tile[i] = d_preds[step*121 + (i % 121)];
    __syncthreads();
    const float4* t4 = (const float4*)tile;
    long base = (long)step * (STEP_SLAB/4) + (long)r * 968;
    int m = t % 121;                        // t < 256
    out[base + t] = t4[m];
    int m1 = m + 14;  if (m1 >= 121) m1 -= 121;   // 256 mod 121 = 14
    out[base + t + 256] = t4[m1];
    int m2 = m1 + 14; if (m2 >= 121) m2 -= 121;
    out[base + t + 512] = t4[m2];
    if (t < 200) {
        int m3 = m2 + 14; if (m3 >= 121) m3 -= 121;
        out[base + t + 768] = t4[m3];
    }
}

// ---------------- launch ----------------
extern "C" void kernel_launch(void* const* d_in, const int* in_sizes, int n_in,
                              void* d_out, int out_size) {
    const float* x          = (const float*)d_in[0];
    const float* conv_w     = (const float*)d_in[3];
    const float* conv_b     = (const float*)d_in[4];
    const float* comp_w1    = (const float*)d_in[5];
    const float* comp_b1    = (const float*)d_in[6];
    const float* comp_w2    = (const float*)d_in[7];
    const float* comp_b2    = (const float*)d_in[8];
    const float* adapter_w  = (const float*)d_in[9];
    const float* adapter_b  = (const float*)d_in[10];
    const float* ln_g       = (const float*)d_in[11];
    const float* ln_b       = (const float*)d_in[12];
    const float* lift_w1    = (const float*)d_in[13];
    const float* lift_b1    = (const float*)d_in[14];
    const float* lift_w2    = (const float*)d_in[15];
    const float* lift_b2    = (const float*)d_in[16];
    const float* net_w1     = (const float*)d_in[17];
    const float* net_b1     = (const float*)d_in[18];
    const float* net_w2     = (const float*)d_in[19];
    const float* net_b2     = (const float*)d_in[20];
    const float* fc1_w      = (const float*)d_in[21];
    const float* fc1_b      = (const float*)d_in[22];
    const float* fc2_w      = (const float*)d_in[23];
    const float* fc2_b      = (const float*)d_in[24];
    const float* fc3_w      = (const float*)d_in[25];
    const float* fc3_b      = (const float*)d_in[26];
    const float* A          = (const float*)d_in[27];
    const float* state_init = (const float*)d_in[28];
    const float* fcout_w    = (const float*)d_in[29];
    const float* fcout_b    = (const float*)d_in[30];
    (void)in_sizes; (void)n_in;

    cudaFuncSetAttribute(k2_chain, cudaFuncAttributeMaxDynamicSharedMemorySize, SMEM_BYTES);

    // fused k1 (32 blocks) + weight pack (256 blocks)
    k0<<<288, 256>>>(x, conv_w, lift_w1, lift_w2, net_w1, net_w2,
                     fc1_w, fc2_w, fc3_w, fcout_w);

    // serial chain on one block
    k2_chain<<<1, 1024, SMEM_BYTES>>>(conv_b, comp_w1, comp_b1, comp_w2, comp_b2,
                                      adapter_w, adapter_b, ln_g, ln_b,
                                      lift_b1, lift_b2, net_b1, net_b2,
                                      fc1_b, fc2_b, fc3_b,
                                      A, state_init, fcout_b);

    // broadcast 6 vectors of 121 into (6,128,24,121)
    k3_bcast<<<576, 256>>>((float4*)d_out);
}

// round 5
// speedup vs baseline: 1.2320x; 1.0336x over previous
#include <cuda_runtime.h>
#include <cuda_fp16.h>
#include <math.h>

// Problem constants
#define NB 128
#define LL 24
#define NN 121
#define DD 121
#define NSTEP 6
#define BL 3072
#define OUT_TOTAL (NSTEP*BL*NN)
#define STEP_SLAB (BL*NN)

// K1 config
#define K1_BLOCKS 32
#define K1_ROWS 96

// Resident pack bases in uint units (each 128-IN matvec: 8192 uints = 16384 halfs)
#define UB_L1 0
#define UB_L2 8192
#define UB_N1 16384      // net1: 2 chunks -> 16384 uints
#define UB_N2 32768
#define UB_F1 40960
#define UPK_TOTAL 49152  // uints -> 196608 bytes

// smem byte offsets
#define SB_PACK   0
#define SB_BIAS   196608   // float[896]
#define SB_RED    200192   // float[4096]
#define SB_CATH2  216576   // uint[256]
#define SB_L1H2   217600   // uint[128]
#define SB_NETH2  218112   // uint[128]
#define SB_XTH2   218624   // uint[128]
#define SB_XTF    219136   // float[128]
#define SB_DELTA  219648   // float[128]
#define SB_BC     220160   // float[128]
#define SB_OUTV   220672   // float[128]
#define SB_OUTVH2 221184   // uint[128]
#define SB_FEAT   221696   // float[128]
#define SB_COMPW  222208   // float[320]
#define SB_DUMMYF 223488   // float[128]
#define SMEM_BYTES 224000

// ---------------- device scratch ----------------
__device__ float d_gpart[K1_BLOCKS * 968];
__device__ float d_preds[NSTEP * DD];
__device__ __align__(16) unsigned int d_hpack[UPK_TOTAL];
__device__ __align__(16) unsigned int d_pk_fc23[8192];
__device__ __align__(16) unsigned int d_pk_fout[8192];

// ---------------- K0: fused k1 partial GEMM + weight packing ----------------
__global__ __launch_bounds__(256)
void k0(const float* __restrict__ x, const float* __restrict__ cw,
        const float* __restrict__ lw1, const float* __restrict__ lw2,
        const float* __restrict__ nw1, const float* __restrict__ nw2,
        const float* __restrict__ f1,  const float* __restrict__ f2,
        const float* __restrict__ f3,  const float* __restrict__ fo) {
    int b = blockIdx.x;
    int t = threadIdx.x;
    if (b < K1_BLOCKS) {
        // ---- k1: g partials, 16-row register preload for MLP=16 ----
        __shared__ float cwsm[K1_ROWS * 8];
        int r0 = b * K1_ROWS;
        for (int j = t; j < K1_ROWS * 8; j += 256) cwsm[j] = cw[r0*8 + j];
        __syncthreads();
        if (t < 121) {
            float acc[8];
#pragma unroll
            for (int j = 0; j < 8; ++j) acc[j] = 0.f;
            const float* xp = x + (long)r0*121 + t;
#pragma unroll 1
            for (int rb = 0; rb < K1_ROWS; rb += 16) {
                float xr[16];
#pragma unroll
                for (int i = 0; i < 16; ++i) xr[i] = xp[(rb + i)*121];
#pragma unroll
                for (int i = 0; i < 16; ++i) {
#pragma unroll
                    for (int j = 0; j < 8; ++j)
                        acc[j] = fmaf(xr[i], cwsm[(rb + i)*8 + j], acc[j]);
                }
            }
#pragma unroll
            for (int j = 0; j < 8; ++j)
                d_gpart[b*968 + j*121 + t] = acc[j];
        }
        return;
    }
    // ---- pack: per (matrix, slice sg): 32 q-groups x 16 halfs ----
    int p = b - K1_BLOCKS;
    int q = t & 31, i = t >> 5;        // i: 0..7 (uint index within (s,q))
    int dl = i >> 1;                   // d_local 0..3
    int ol = (2*i) & 3;                // 0 or 2
    int m, sg;
    if      (p < 32)  { m = 0; sg = p; }
    else if (p < 64)  { m = 1; sg = p - 32; }
    else if (p < 128) { m = 2; sg = p - 64; }
    else if (p < 160) { m = 3; sg = p - 128; }
    else if (p < 192) { m = 4; sg = p - 160; }
    else if (p < 224) { m = 5; sg = p - 192; }
    else              { m = 6; sg = p - 224; }
    int k = sg*4 + dl;                 // packed input index
    int row, rvalid;
    if (m == 2) {
        row = (k < 128) ? k : (121 + (k - 128));
        rvalid = (k < 128) ? (k < 121) : ((k - 128) < 121);
    } else {
        row = k;
        rvalid = (k < ((m == 1 || m == 3) ? 128 : 121));
    }
    int o0 = q*4 + ol, o1 = o0 + 1;
    float v0 = 0.f, v1 = 0.f;
    if (rvalid) {
        switch (m) {
            case 0: v0 = lw1[row*128 + o0]; v1 = lw1[row*128 + o1]; break;
            case 1: v0 = (o0 < 121) ? lw2[row*121 + o0] : 0.f;
                    v1 = (o1 < 121) ? lw2[row*121 + o1] : 0.f; break;
            case 2: v0 = nw1[row*128 + o0]; v1 = nw1[row*128 + o1]; break;
            case 3: v0 = (o0 < 121) ? nw2[row*121 + o0] : 0.f;
                    v1 = (o1 < 121) ? nw2[row*121 + o1] : 0.f; break;
            case 4: v0 = (o0 < 121) ? f1[row*121 + o0] : 0.f;
                    v1 = (o1 < 121) ? f1[row*121 + o1] : 0.f; break;
            case 5: v0 = (o0 < 64) ? f2[row*64 + o0] : f3[row*64 + o0 - 64];
                    v1 = (o1 < 64) ? f2[row*64 + o1] : f3[row*64 + o1 - 64]; break;
            default:v0 = (o0 < 121) ? fo[row*121 + o0] : 0.f;
                    v1 = (o1 < 121) ? fo[row*121 + o1] : 0.f; break;
        }
    }
    __half2 hh = __floats2half2_rn(v0, v1);
    unsigned u = *(unsigned*)&hh;
    unsigned* dp; unsigned base;
    switch (m) {
        case 0: dp = d_hpack;   base = UB_L1; break;
        case 1: dp = d_hpack;   base = UB_L2; break;
        case 2: dp = d_hpack;   base = UB_N1; break;
        case 3: dp = d_hpack;   base = UB_N2; break;
        case 4: dp = d_hpack;   base = UB_F1; break;
        case 5: dp = d_pk_fc23; base = 0; break;
        default:dp = d_pk_fout; base = 0; break;
    }
    dp[base + (unsigned)(sg*32 + q)*8u + i] = u;
}

// ---------------- activations ----------------
#define ACT_NONE 0
#define ACT_RELU 1
#define ACT_TANH 2
#define ACT_SOFTPLUS 3

template<int ACT>
__device__ __forceinline__ float actfn(float v) {
    if (ACT == ACT_RELU) return v > 0.f ? v : 0.f;
    if (ACT == ACT_TANH) return tanhf(v);
    if (ACT == ACT_SOFTPLUS) return v > 20.f ? v : log1pf(expf(v));
    return v;
}

// ---------------- cp.async helpers ----------------
__device__ __forceinline__ void cp_async16(void* smem_dst, const void* gsrc) {
    unsigned saddr = (unsigned)__cvta_generic_to_shared(smem_dst);
    asm volatile("cp.async.cg.shared.global [%0], [%1], 16;" :: "r"(saddr), "l"(gsrc));
}

// ---------------- half2 matvec: 128 outputs, 32 slices x 4 inputs ----------------
template<int ACT, int CHUNKS>
__device__ __forceinline__ void mvh(const uint4* __restrict__ Wt,
                                    const float* __restrict__ biasp,
                                    const unsigned* __restrict__ inh2,
                                    float* __restrict__ outf,
                                    unsigned* __restrict__ outh2,
                                    float* __restrict__ red) {
    int tid = threadIdx.x;
    int q = tid & 31, s = tid >> 5;
    float2 a01 = make_float2(0.f, 0.f), a23 = make_float2(0.f, 0.f);
#pragma unroll
    for (int c = 0; c < CHUNKS; ++c) {
        uint4 xh = ((const uint4*)inh2)[c*32 + s];
        const uint4* wp = Wt + ((c*32 + s)*32 + q)*2;
        uint4 w0 = wp[0];
        uint4 w1 = wp[1];
        __half2 x0 = *(__half2*)&xh.x, x1 = *(__half2*)&xh.y;
        __half2 x2 = *(__half2*)&xh.z, x3 = *(__half2*)&xh.w;
        __half2 p01 = __hfma2(x0, *(__half2*)&w0.x, __hmul2(x1, *(__half2*)&w0.z));
        __half2 p23 = __hfma2(x0, *(__half2*)&w0.y, __hmul2(x1, *(__half2*)&w0.w));
        float2 f;
        f = __half22float2(p01); a01.x += f.x; a01.y += f.y;
        f = __half22float2(p23); a23.x += f.x; a23.y += f.y;
        p01 = __hfma2(x2, *(__half2*)&w1.x, __hmul2(x3, *(__half2*)&w1.z));
        p23 = __hfma2(x2, *(__half2*)&w1.y, __hmul2(x3, *(__half2*)&w1.w));
        f = __half22float2(p01); a01.x += f.x; a01.y += f.y;
        f = __half22float2(p23); a23.x += f.x; a23.y += f.y;
    }
    ((float4*)red)[s*32 + q] = make_float4(a01.x, a01.y, a23.x, a23.y);
    __syncthreads();
    if (tid < 128) {
        float v = 0.f;
#pragma unroll
        for (int ss = 0; ss < 32; ++ss) v += red[ss*128 + tid];
        v += biasp[tid];
        v = actfn<ACT>(v);
        outf[tid] = v;
        __half2 d2 = __half2half2(__float2half_rn(v));
        outh2[tid] = *(unsigned*)&d2;
    }
    __syncthreads();
}

// ---------------- K2: whole serial chain in one block ----------------
__global__ __launch_bounds__(1024, 1)
void k2_chain(const float* __restrict__ conv_b,
              const float* __restrict__ comp_w1, const float* __restrict__ comp_b1,
              const float* __restrict__ comp_w2, const float* __restrict__ comp_b2,
              const float* __restrict__ adapter_w, const float* __restrict__ adapter_b,
              const float* __restrict__ ln_g, const float* __restrict__ ln_b,
              const float* __restrict__ lift_b1, const float* __restrict__ lift_b2,
              const float* __restrict__ net_b1, const float* __restrict__ net_b2,
              const float* __restrict__ fc1_b,
              const float* __restrict__ fc2_b, const float* __restrict__ fc3_b,
              const float* __restrict__ Ag, const float* __restrict__ state_init,
              const float* __restrict__ fcout_b) {
    extern __shared__ __align__(16) unsigned char smraw[];
    float*    biasp   = (float*)(smraw + SB_BIAS);
    float*    red     = (float*)(smraw + SB_RED);
    unsigned* cath2   = (unsigned*)(smraw + SB_CATH2);
    unsigned* l1h2    = (unsigned*)(smraw + SB_L1H2);
    unsigned* neth2   = (unsigned*)(smraw + SB_NETH2);
    unsigned* xth2    = (unsigned*)(smraw + SB_XTH2);
    float*    xtf     = (float*)(smraw + SB_XTF);
    float*    delta_s = (float*)(smraw + SB_DELTA);
    float*    bc      = (float*)(smraw + SB_BC);
    float*    outv    = (float*)(smraw + SB_OUTV);
    unsigned* outvh2  = (unsigned*)(smraw + SB_OUTVH2);
    float*    feat    = (float*)(smraw + SB_FEAT);
    float*    compw   = (float*)(smraw + SB_COMPW);
    float*    dummyf  = (float*)(smraw + SB_DUMMYF);

    const uint4* W_L1 = (const uint4*)(smraw + UB_L1*4);
    const uint4* W_L2 = (const uint4*)(smraw + UB_L2*4);
    const uint4* W_N1 = (const uint4*)(smraw + UB_N1*4);
    const uint4* W_N2 = (const uint4*)(smraw + UB_N2*4);
    const uint4* W_F1 = (const uint4*)(smraw + UB_F1*4);
    const uint4* W_FC23 = (const uint4*)d_pk_fc23;
    const uint4* W_FOUT = (const uint4*)d_pk_fout;

    int tid = threadIdx.x;

    // --- 0. async prefetch of resident pack into smem ---
    {
        const uint4* src = (const uint4*)d_hpack;
        for (int i = tid; i < UPK_TOTAL/4; i += 1024)
            cp_async16((uint4*)smraw + i, src + i);
        asm volatile("cp.async.commit_group;");
    }

    // --- 1. reduce GEMM partials -> g in red[n*8+j] ---
    if (tid < 968) {
        int j = tid / 121, n = tid % 121;
        float v = conv_b[j];
#pragma unroll 4
        for (int b = 0; b < K1_BLOCKS; ++b) v += d_gpart[b*968 + tid];
        red[n*8 + j] = v;
    }
    __syncthreads();
    if (tid < 256) compw[tid] = comp_w1[tid] + comp_w1[256 + tid];
    else if (tid < 288) compw[tid] = comp_b1[tid - 256];
    else if (tid < 320) compw[tid] = comp_w2[tid - 288];
    if (tid < 896) {
        int seg = tid >> 7, j = tid & 127;
        float v = 0.f;
        if (seg == 0) v = lift_b1[j];
        else if (seg == 1) v = (j < 121) ? lift_b2[j] : 0.f;
        else if (seg == 2) v = net_b1[j];
        else if (seg == 3) v = (j < 121) ? net_b2[j] : 0.f;
        else if (seg == 4) v = (j < 121) ? fc1_b[j] : 0.f;
        else if (seg == 5) v = (j < 64) ? fc2_b[j] : fc3_b[j - 64];
        else v = (j < 121) ? fcout_b[j] : 0.f;
        biasp[tid] = v;
    }
    if (tid >= 121 && tid < 128) { cath2[tid] = 0u; outvh2[tid] = 0u; }
    __syncthreads();

    // --- 2. feature compressor -> feat[n] ---
    if (tid < 121) {
        float gv[8];
#pragma unroll
        for (int j = 0; j < 8; ++j) gv[j] = red[tid*8 + j];
        float f = comp_b2[0];
#pragma unroll 4
        for (int kk = 0; kk < 32; ++kk) {
            float hh = compw[256 + kk];
#pragma unroll
            for (int i = 0; i < 8; ++i) hh = fmaf(gv[i], compw[i*32 + kk], hh);
            hh = hh > 0.f ? hh : 0.01f * hh;
            f = fmaf(hh, compw[288 + kk], f);
        }
        feat[tid] = f;
    }
    __syncthreads();

    // --- 3. adapter matvec (one-time) ---
    if (tid < 121) {
        float v = adapter_b[tid];
        for (int n = 0; n < 121; ++n) v = fmaf(feat[n], adapter_w[n*121 + tid], v);
        outv[tid] = v;
    }
    __syncthreads();

    // --- 4. layernorm -> q into cath2[0..120] (dup-half2) ---
    {
        float zv = (tid < 121) ? outv[tid] : 0.f;
        red[tid] = zv;
        red[1024 + tid] = zv * zv;
        __syncthreads();
        for (int off = 512; off > 0; off >>= 1) {
            if (tid < off) {
                red[tid] += red[tid + off];
                red[1024 + tid] += red[1024 + tid + off];
            }
            __syncthreads();
        }
        float mu = red[0] * (1.f / 121.f);
        float var = red[1024] * (1.f / 121.f) - mu * mu;
        float rstd = rsqrtf(var + 1e-5f);
        if (tid < 121) {
            float qv = (outv[tid] - mu) * rstd * ln_g[tid] + ln_b[tid];
            __half2 d2 = __half2half2(__float2half_rn(qv));
            cath2[tid] = *(unsigned*)&d2;
        }
    }

    // --- 5. state h + A in registers ---
    float h[8], av[8];
    int sd = tid >> 3, s8 = tid & 7;
    int hbase = sd * 64 + s8 * 8;
    if (tid < 968) {
        float4 h0 = *(const float4*)(state_init + hbase);
        float4 h1 = *(const float4*)(state_init + hbase + 4);
        h[0]=h0.x; h[1]=h0.y; h[2]=h0.z; h[3]=h0.w;
        h[4]=h1.x; h[5]=h1.y; h[6]=h1.z; h[7]=h1.w;
        float4 a0 = *(const float4*)(Ag + hbase);
        float4 a1 = *(const float4*)(Ag + hbase + 4);
        av[0]=a0.x; av[1]=a0.y; av[2]=a0.z; av[3]=a0.w;
        av[4]=a1.x; av[5]=a1.y; av[6]=a1.z; av[7]=a1.w;
    }
    asm volatile("cp.async.wait_group 0;");
    __syncthreads();

    // --- 6. 7 serial mamba iterations (iter 0 = warmup) ---
#pragma unroll 1
    for (int it = 0; it < 7; ++it) {
        mvh<ACT_RELU, 1>(W_L1, biasp + 0,   cath2, dummyf, l1h2,        red);
        mvh<ACT_TANH, 1>(W_L2, biasp + 128, l1h2,  dummyf, cath2 + 128, red);
        mvh<ACT_RELU, 2>(W_N1, biasp + 256, cath2, dummyf, neth2,       red);
        mvh<ACT_NONE, 1>(W_N2, biasp + 384, neth2, xtf,    xth2,        red);
        mvh<ACT_SOFTPLUS, 1>(W_F1, biasp + 512, xth2, delta_s, l1h2,    red);
        mvh<ACT_NONE, 1>(W_FC23, biasp + 640, xth2, bc, l1h2,           red);

        // state update + partial out
        if (tid < 968) {
            float dl = delta_s[sd];
            float xd = xtf[sd] * dl;
            float po = 0.f;
#pragma unroll
            for (int j = 0; j < 8; ++j) {
                float z = dl * av[j];
                float cel = z > 0.f ? z : expm1f(z);
                float dA = expf(-cel);
                float hn = fmaf(dA, h[j], xd * bc[s8*8 + j]);
                h[j] = hn;
                po = fmaf(bc[64 + s8*8 + j], hn, po);
            }
            red[tid] = po;
        }
        __syncthreads();
        if (tid < 121) {
            float v = 0.f;
#pragma unroll
            for (int s2 = 0; s2 < 8; ++s2) v += red[tid*8 + s2];
            outv[tid] = v;
            __half2 d2 = __half2half2(__float2half_rn(v));
            outvh2[tid] = *(unsigned*)&d2;
        }
        __syncthreads();

        if (it > 0) {
            mvh<ACT_NONE, 1>(W_FOUT, biasp + 768, outvh2, dummyf, cath2, red);
            if (tid < 121) d_preds[(it - 1)*121 + tid] = dummyf[tid];
        }
        // it == 0: q (cath2[0..127]) untouched -> stays z0
    }
}

// ---------------- K3: coalesced broadcast (576 blocks x 256 thr) ----------------
__global__ __launch_bounds__(256)
void k3_bcast(float4* __restrict__ out) {
    __shared__ __align__(16) float tile[484];
    int b = blockIdx.x;
    int step = b / 96;
    int r = b - step * 96;
    int t = threadIdx.x;
    for (int i = t; i < 484; i += 256) tile[i] = d_preds[step*121 + (i % 121)];
    __syncthreads();
    const float4* t4 = (const float4*)tile;
    long base = (long)step * (STEP_SLAB/4) + (long)r * 968;
    int m = t % 121;
    out[base + t] = t4[m];
    int m1 = m + 14;  if (m1 >= 121) m1 -= 121;
    out[base + t + 256] = t4[m1];
    int m2 = m1 + 14; if (m2 >= 121) m2 -= 121;
    out[base + t + 512] = t4[m2];
    if (t < 200) {
        int m3 = m2 + 14; if (m3 >= 121) m3 -= 121;
        out[base + t + 768] = t4[m3];
    }
}

// ---------------- launch ----------------
extern "C" void kernel_launch(void* const* d_in, const int* in_sizes, int n_in,
                              void* d_out, int out_size) {
    const float* x          = (const float*)d_in[0];
    const float* conv_w     = (const float*)d_in[3];
    const float* conv_b     = (const float*)d_in[4];
    const float* comp_w1    = (const float*)d_in[5];
    const float* comp_b1    = (const float*)d_in[6];
    const float* comp_w2    = (const float*)d_in[7];
    const float* comp_b2    = (const float*)d_in[8];
    const float* adapter_w  = (const float*)d_in[9];
    const float* adapter_b  = (const float*)d_in[10];
    const float* ln_g       = (const float*)d_in[11];
    const float* ln_b       = (const float*)d_in[12];
    const float* lift_w1    = (const float*)d_in[13];
    const float* lift_b1    = (const float*)d_in[14];
    const float* lift_w2    = (const float*)d_in[15];
    const float* lift_b2    = (const float*)d_in[16];
    const float* net_w1     = (const float*)d_in[17];
    const float* net_b1     = (const float*)d_in[18];
    const float* net_w2     = (const float*)d_in[19];
    const float* net_b2     = (const float*)d_in[20];
    const float* fc1_w      = (const float*)d_in[21];
    const float* fc1_b      = (const float*)d_in[22];
    const float* fc2_w      = (const float*)d_in[23];
    const float* fc2_b      = (const float*)d_in[24];
    const float* fc3_w      = (const float*)d_in[25];
    const float* fc3_b      = (const float*)d_in[26];
    const float* A          = (const float*)d_in[27];
    const float* state_init = (const float*)d_in[28];
    const float* fcout_w    = (const float*)d_in[29];
    const float* fcout_b    = (const float*)d_in[30];
    (void)in_sizes; (void)n_in;

    cudaFuncSetAttribute(k2_chain, cudaFuncAttributeMaxDynamicSharedMemorySize, SMEM_BYTES);

    // fused k1 (32 blocks, MLP=16) + weight pack (256 blocks)
    k0<<<288, 256>>>(x, conv_w, lift_w1, lift_w2, net_w1, net_w2,
                     fc1_w, fc2_w, fc3_w, fcout_w);

    // serial chain on one block
    k2_chain<<<1, 1024, SMEM_BYTES>>>(conv_b, comp_w1, comp_b1, comp_w2, comp_b2,
                                      adapter_w, adapter_b, ln_g, ln_b,
                                      lift_b1, lift_b2, net_b1, net_b2,
                                      fc1_b, fc2_b, fc3_b,
                                      A, state_init, fcout_b);

    // broadcast 6 vectors of 121 into (6,128,24,121)
    k3_bcast<<<576, 256>>>((float4*)d_out);
}